// round 16
// baseline (speedup 1.0000x reference)
#include <cuda_runtime.h>
#include <cuda_bf16.h>
#include <cstdint>

#define BROWS 8192
#define NF 1024
#define KTOT 13312              // 13 terms x 1024 along fused K axis

#define PA 4096                 // build_A blocks
#define PW 13312                // prep_W blocks (13 x 32 x 32)
#define PB 4                    // bias blocks
#define NPREP (PA + PW + PB)

__device__ __align__(256) __nv_bfloat16 g_A[(size_t)BROWS * KTOT];  // [row][t*1024+k]
__device__ __align__(256) __nv_bfloat16 g_W[(size_t)NF * KTOT];     // [n][t*1024+k]
__device__ __align__(256) __nv_bfloat16 g_O[(size_t)BROWS * NF];    // bf16 chain / pre-RMS out
__device__ __align__(256) __nv_bfloat16 g_bias[NF];
__device__ __align__(256) unsigned short g_lut[65536];              // silu(bf16) -> bf16 bits

__device__ __forceinline__ uint32_t smem_u32(const void* p) {
    uint32_t a;
    asm("{ .reg .u64 t; cvta.to.shared.u64 t, %1; cvt.u32.u64 %0, t; }" : "=r"(a) : "l"(p));
    return a;
}
__device__ __forceinline__ void cp16(uint32_t d, const void* s) {
    asm volatile("cp.async.cg.shared.global [%0], [%1], 16;" :: "r"(d), "l"(s) : "memory");
}
__device__ __forceinline__ void ldsm4(uint32_t* r, uint32_t a) {
    asm volatile("ldmatrix.sync.aligned.m8n8.x4.shared.b16 {%0,%1,%2,%3}, [%4];"
        : "=r"(r[0]), "=r"(r[1]), "=r"(r[2]), "=r"(r[3]) : "r"(a));
}
__device__ __forceinline__ void mma16816(float* c, const uint32_t* a, uint32_t b0, uint32_t b1) {
    asm volatile("mma.sync.aligned.m16n8k16.row.col.f32.bf16.bf16.f32 "
        "{%0,%1,%2,%3}, {%4,%5,%6,%7}, {%8,%9}, {%0,%1,%2,%3};"
        : "+f"(c[0]), "+f"(c[1]), "+f"(c[2]), "+f"(c[3])
        : "r"(a[0]), "r"(a[1]), "r"(a[2]), "r"(a[3]), "r"(b0), "r"(b1));
}
__device__ __forceinline__ uint32_t cvt2(float hi, float lo) {
    uint32_t d; asm("cvt.rn.bf16x2.f32 %0, %1, %2;" : "=r"(d) : "f"(hi), "f"(lo)); return d;
}
__device__ __forceinline__ uint32_t badd2(uint32_t a, uint32_t b) {
    uint32_t d; asm("add.rn.bf16x2 %0, %1, %2;" : "=r"(d) : "r"(a), "r"(b)); return d;
}
__device__ __forceinline__ uint32_t swz(uint32_t off) { return off ^ ((off >> 3) & 0x70); }

// ---- kernel 0: silu LUT over all 65536 bf16 inputs ----
__global__ __launch_bounds__(256) void kan_lut() {
    int i = blockIdx.x * 256 + threadIdx.x;
    unsigned short us = (unsigned short)i;
    __nv_bfloat16 xb = __ushort_as_bfloat16(us);
    float xf = __bfloat162float(xb);
    float ee = __bfloat162float(__float2bfloat16(expf(-xf)));
    float dd = __bfloat162float(__float2bfloat16(1.0f + ee));
    float s  = __bfloat162float(__float2bfloat16(1.0f / dd));
    g_lut[i] = __bfloat16_as_ushort(__float2bfloat16(xf * s));
}

// ---- kernel 1: fused prologue — three independent block regions ----
__global__ __launch_bounds__(256) void kan_prep(const float* __restrict__ x,
                                                const float* __restrict__ bw,
                                                const float* __restrict__ pw) {
    int bid = blockIdx.x, tid = threadIdx.x;
    if (bid < PA) {
        // ===== build_A: 8 columns/thread; silu via LUT, tanh + Chebyshev in f32 =====
        size_t u = (size_t)bid * 256 + tid;
        size_t r = u >> 7, grp = u & 127;
        const float4* xp = reinterpret_cast<const float4*>(x + r * NF + grp * 8);
        float4 a4 = xp[0], b4 = xp[1];
        float xv[8] = {a4.x, a4.y, a4.z, a4.w, b4.x, b4.y, b4.z, b4.w};
        __nv_bfloat16* row = g_A + r * KTOT + grp * 8;
        uint32_t a0b[8];
        float xs[8], Tp[8], Tc[8];
#pragma unroll
        for (int e = 0; e < 8; e++) {
            unsigned short ib = __bfloat16_as_ushort(__float2bfloat16(xv[e]));
            a0b[e] = (uint32_t)g_lut[ib];
            xs[e] = tanhf(xv[e]);
            Tp[e] = 1.0f; Tc[e] = xs[e];
        }
        *reinterpret_cast<uint4*>(row) =
            make_uint4(a0b[0] | (a0b[1] << 16), a0b[2] | (a0b[3] << 16),
                       a0b[4] | (a0b[5] << 16), a0b[6] | (a0b[7] << 16));
        *reinterpret_cast<uint4*>(row + 1024) =
            make_uint4(cvt2(xs[1], xs[0]), cvt2(xs[3], xs[2]), cvt2(xs[5], xs[4]), cvt2(xs[7], xs[6]));
#pragma unroll
        for (int k = 2; k <= 12; k++) {
            float Tn[8];
#pragma unroll
            for (int e = 0; e < 8; e++) {
                Tn[e] = 2.0f * xs[e] * Tc[e] - Tp[e];
                Tp[e] = Tc[e]; Tc[e] = Tn[e];
            }
            *reinterpret_cast<uint4*>(row + (size_t)k * 1024) =
                make_uint4(cvt2(Tn[1], Tn[0]), cvt2(Tn[3], Tn[2]), cvt2(Tn[5], Tn[4]), cvt2(Tn[7], Tn[6]));
        }
    } else if (bid < PA + PW) {
        // ===== prep_W: transpose one 32x32 tile of term t =====
        __shared__ float tile[32][33];
        int w = bid - PA;
        int t = w >> 10, rr = w & 1023;
        int n0 = (rr & 31) * 32, k0 = (rr >> 5) * 32;
        const float* src = (t == 0) ? bw : (pw + (size_t)t * NF * NF);
        int tx = tid & 31, ty = tid >> 5;   // 32 x 8
#pragma unroll
        for (int i = 0; i < 4; i++)
            tile[ty + i * 8][tx] = src[(size_t)(k0 + ty + i * 8) * NF + n0 + tx];
        __syncthreads();
#pragma unroll
        for (int i = 0; i < 4; i++)
            g_W[(size_t)(n0 + ty + i * 8) * KTOT + t * 1024 + k0 + tx] = __float2bfloat16(tile[tx][ty + i * 8]);
    } else {
        // ===== bias: bf16( f32 colsum of bf16(pw[0]) ) =====
        int n = (bid - PA - PW) * 256 + tid;
        float a = 0.0f;
        for (int k = 0; k < NF; k++)
            a += __bfloat162float(__float2bfloat16(pw[(size_t)k * NF + n]));
        g_bias[n] = __float2bfloat16(a);
    }
}

// ---- kernel 2: 128x128-tile GEMM, 2 CTAs/SM, ks-level fragment pipelining ----
#define STG_B 32768u            // A 128x64 (16KB) + W 128x64 (16KB)
#define SMEM_SZ (3 * 32768)
#define NCHUNK 208              // 13312/64; term t = chunk>>4

__device__ __forceinline__ void load_chunk(uint32_t sb, int g, int tid, int m0, int n0) {
    uint32_t stg = sb + (uint32_t)(g % 3) * STG_B;
    const __nv_bfloat16* Ab = g_A + (size_t)m0 * KTOT + g * 64;
    const __nv_bfloat16* Wb = g_W + (size_t)n0 * KTOT + g * 64;
#pragma unroll
    for (int k = 0; k < 8; k++) {
        int i = tid + k * 256;
        int half_ = i >> 10, j = i & 1023, r = j >> 3, s = j & 7;
        const __nv_bfloat16* src = (half_ ? Wb : Ab) + (size_t)r * KTOT + s * 8;
        cp16(stg + (half_ ? 16384u : 0u) + swz((uint32_t)(r * 128 + s * 16)), src);
    }
}

__global__ __launch_bounds__(256, 2) void kan_gemm() {
    extern __shared__ char smem[];
    uint32_t sb = smem_u32(smem);
    int tid = threadIdx.x, wid = tid >> 5, lane = tid & 31;
    int m0 = (blockIdx.x >> 3) * 128, n0 = (blockIdx.x & 7) * 128;
    int mw = wid >> 1, nw = wid & 1;          // 4x2 warp grid, warp tile 32x64
    uint32_t rowA0 = (uint32_t)((mw * 32 + (lane & 15)) * 128);
    uint32_t rowB0 = (uint32_t)((nw * 64 + (lane & 15)) * 128);
    uint32_t kbase = (uint32_t)((lane >> 4) * 16);

    float acc[2][8][4];
#pragma unroll
    for (int a = 0; a < 2; a++)
#pragma unroll
        for (int b = 0; b < 8; b++)
#pragma unroll
            for (int r = 0; r < 4; r++) acc[a][b][r] = 0.0f;

    uint32_t afr[2][2][4];
    uint32_t bfr[2][4][4];

    load_chunk(sb, 0, tid, m0, n0);
    asm volatile("cp.async.commit_group;" ::: "memory");
    load_chunk(sb, 1, tid, m0, n0);
    asm volatile("cp.async.commit_group;" ::: "memory");

    for (int g = 0; g < NCHUNK; g++) {
        asm volatile("cp.async.wait_group 1;" ::: "memory");
        __syncthreads();
        uint32_t stA = sb + (uint32_t)(g % 3) * STG_B;
        uint32_t stB = stA + 16384u;
        {
            uint32_t ko = kbase;
            ldsm4(afr[0][0], stA + swz(rowA0 + ko));
            ldsm4(afr[0][1], stA + swz(rowA0 + 2048 + ko));
            ldsm4(bfr[0][0], stB + swz(rowB0 + ko));
            ldsm4(bfr[0][1], stB + swz(rowB0 + 2048 + ko));
            ldsm4(bfr[0][2], stB + swz(rowB0 + 4096 + ko));
            ldsm4(bfr[0][3], stB + swz(rowB0 + 6144 + ko));
        }
#pragma unroll
        for (int ks = 0; ks < 4; ks++) {
            int cur = ks & 1, nxt = cur ^ 1;
#pragma unroll
            for (int ni = 0; ni < 8; ni++)
                mma16816(acc[0][ni], afr[cur][0], bfr[cur][ni >> 1][ni & 1], bfr[cur][ni >> 1][(ni & 1) + 2]);
            if (ks < 3) {
                uint32_t ko = kbase + (uint32_t)(ks + 1) * 32;
                ldsm4(afr[nxt][0], stA + swz(rowA0 + ko));
                ldsm4(afr[nxt][1], stA + swz(rowA0 + 2048 + ko));
                ldsm4(bfr[nxt][0], stB + swz(rowB0 + ko));
                ldsm4(bfr[nxt][1], stB + swz(rowB0 + 2048 + ko));
                ldsm4(bfr[nxt][2], stB + swz(rowB0 + 4096 + ko));
                ldsm4(bfr[nxt][3], stB + swz(rowB0 + 6144 + ko));
            }
#pragma unroll
            for (int ni = 0; ni < 8; ni++)
                mma16816(acc[1][ni], afr[cur][1], bfr[cur][ni >> 1][ni & 1], bfr[cur][ni >> 1][(ni & 1) + 2]);
        }
        if (g + 2 < NCHUNK) load_chunk(sb, g + 2, tid, m0, n0);
        asm volatile("cp.async.commit_group;" ::: "memory");

        if ((g & 15) == 15) {   // term boundary: round term, bf16-add into global chain
            int t = g >> 4;
            int rb = m0 + mw * 32 + (lane >> 2);
            int cb = n0 + nw * 64 + (lane & 3) * 2;
            uint32_t* chain0 = reinterpret_cast<uint32_t*>(g_O + (size_t)rb * NF + cb);
            uint32_t* chain1 = reinterpret_cast<uint32_t*>(g_O + (size_t)(rb + 8) * NF + cb);
            const uint32_t* bp = reinterpret_cast<const uint32_t*>(g_bias) + (cb >> 1);
#pragma unroll
            for (int mi = 0; mi < 2; mi++)
#pragma unroll
                for (int ni = 0; ni < 8; ni++) {
                    uint32_t lo = cvt2(acc[mi][ni][1], acc[mi][ni][0]);
                    uint32_t hi = cvt2(acc[mi][ni][3], acc[mi][ni][2]);
                    int off = mi * 16 * (NF / 2) + ni * 4;
                    if (t == 0) {
                        uint32_t bv = bp[ni * 4];
                        chain0[off] = badd2(lo, bv);
                        chain1[off] = badd2(hi, bv);
                    } else {
                        chain0[off] = badd2(chain0[off], lo);
                        chain1[off] = badd2(chain1[off], hi);
                    }
#pragma unroll
                    for (int r = 0; r < 4; r++) acc[mi][ni][r] = 0.0f;
                }
        }
    }
}

// ---- kernel 3: RMSNorm (bf16 in, fp32 math/out) ----
__global__ __launch_bounds__(256) void kan_rms(const float* __restrict__ scale, float* __restrict__ out) {
    int row = blockIdx.x, tid = threadIdx.x;
    uint2 d = *reinterpret_cast<const uint2*>(g_O + (size_t)row * NF + tid * 4);
    float v0 = __uint_as_float(d.x << 16), v1 = __uint_as_float(d.x & 0xFFFF0000u);
    float v2 = __uint_as_float(d.y << 16), v3 = __uint_as_float(d.y & 0xFFFF0000u);
    float ss = v0 * v0 + v1 * v1 + v2 * v2 + v3 * v3;
#pragma unroll
    for (int o = 16; o; o >>= 1) ss += __shfl_xor_sync(0xFFFFFFFFu, ss, o);
    __shared__ float red[8];
    if ((tid & 31) == 0) red[tid >> 5] = ss;
    __syncthreads();
    float tot = red[0] + red[1] + red[2] + red[3] + red[4] + red[5] + red[6] + red[7];
    float inv = rsqrtf(tot * (1.0f / 1024.0f) + 1e-6f);
    float4 o4;
    o4.x = v0 * inv * scale[tid * 4 + 0];
    o4.y = v1 * inv * scale[tid * 4 + 1];
    o4.z = v2 * inv * scale[tid * 4 + 2];
    o4.w = v3 * inv * scale[tid * 4 + 3];
    *reinterpret_cast<float4*>(out + (size_t)row * NF + tid * 4) = o4;
}

extern "C" void kernel_launch(void* const* d_in, const int* in_sizes, int n_in,
                              void* d_out, int out_size) {
    const float *x = nullptr, *bw = nullptr, *pw = nullptr, *sc = nullptr;
    for (int i = 0; i < n_in; i++) {
        if (in_sizes[i] == 8388608)       x  = (const float*)d_in[i];
        else if (in_sizes[i] == 1048576)  bw = (const float*)d_in[i];
        else if (in_sizes[i] == 13631488) pw = (const float*)d_in[i];
        else if (in_sizes[i] == 1024)     sc = (const float*)d_in[i];
    }
    cudaFuncSetAttribute(kan_gemm, cudaFuncAttributeMaxDynamicSharedMemorySize, SMEM_SZ);
    kan_lut<<<256, 256>>>();
    kan_prep<<<NPREP, 256>>>(x, bw, pw);
    kan_gemm<<<512, 256, SMEM_SZ>>>();
    kan_rms<<<BROWS, 256>>>(sc, (float*)d_out);
}